// round 7
// baseline (speedup 1.0000x reference)
#include <cuda_runtime.h>
#include <cstdint>

// Problem shape (fixed for this dataset entry)
#define B_    2
#define N_    50000
#define C_    64
#define M_    50000
#define K_    16
#define H_    8
#define CMID_ 16

// Runtime-detected index width flag (int64 vs int32), set by detect kernel.
__device__ int g_idx_is64;

__global__ void detect_idx_kernel(const unsigned int* __restrict__ w) {
    if (threadIdx.x == 0 && blockIdx.x == 0) {
        int is64 = 1;
        #pragma unroll 1
        for (int i = 0; i < 256; i++) {
            if (w[2 * i + 1] != 0u) { is64 = 0; break; }
        }
        g_idx_is64 = is64;
    }
}

// One WARP per point; 4 points per 128-thread CTA.
// Lane l: cg = l&7 owns 8 contiguous channels [8cg,8cg+8) == ONE guidance
// head; jq = l>>3 owns w quad [4jq,4jq+4).
// Minimal per-k L1 budget (lane-byte wavefront model):
//   2 LDG.128 gather (4-dup, ~2 wf ea) + 1 scalar guid LDS (1 wf)
//   + ONE W LDS.128 (4 wf)  ==> ~9 wf/k, lowest of all tilings that fit regs.
// Arithmetic per k: 1 dup + 4 mul.rn.f32x2 (channel-pairs straight from the
// gather load) + 4 W dups + 16 fma.rn.f32x2.
// acc[i*4+j] = {out[8cg+2i][4jq+j], out[8cg+2i+1][4jq+j]}.
// Register discipline: depth-1 double buffer, unroll 4, bounds(128,7).
__global__ void __launch_bounds__(128, 7)
pcf_kernel(const float* __restrict__ feat,
           const void*  __restrict__ inds_raw,
           const float* __restrict__ guid,
           const float* __restrict__ wn,
           float* __restrict__ out)
{
    __shared__ __align__(16) float swn[4][K_ * CMID_];  // 4 x 1KB  weightnet
    __shared__ __align__(16) float sgd[4][K_ * H_];     // 4 x 512B guidance
    __shared__ int sidx[4][K_];

    const int wid  = threadIdx.x >> 5;
    const int lane = threadIdx.x & 31;
    const int p    = blockIdx.x * 4 + wid;      // point id in [0, B*M)
    const int b    = (p >= M_) ? 1 : 0;
    const int cg   = lane & 7;                  // channel group (== head)
    const int jq   = lane >> 3;                 // w quad 0..3

    // ---- per-warp staging: weightnet (1KB), guidance (512B), indices ----
    {
        const float4* wsrc = (const float4*)(wn + (size_t)p * (K_ * CMID_));
        float4* wdst = (float4*)(swn[wid]);
        wdst[lane]      = wsrc[lane];
        wdst[lane + 32] = wsrc[lane + 32];
        ((float4*)(sgd[wid]))[lane] = ((const float4*)(guid + (size_t)p * (K_ * H_)))[lane];
        if (lane < K_) {
            long long idx;
            if (g_idx_is64) idx = ((const long long*)inds_raw)[(size_t)p * K_ + lane];
            else            idx = (long long)((const int*)inds_raw)[(size_t)p * K_ + lane];
            sidx[wid][lane] = (int)idx;
        }
    }
    __syncwarp();

    // lane-fixed channel base: this lane's 8 channels start at 8*cg
    const float* fb = feat + (size_t)b * ((size_t)N_ * C_) + 8 * cg;

    unsigned long long acc[16];
    #pragma unroll
    for (int i = 0; i < 16; i++) acc[i] = 0ull;

    // depth-1 double buffer: one row (2 x LDG.128) in flight ahead
    ulonglong2 A0, A1;
    {
        const ulonglong2* r = (const ulonglong2*)(fb + (size_t)sidx[wid][0] * C_);
        A0 = r[0]; A1 = r[1];
    }

    #pragma unroll 4
    for (int k = 0; k < K_; k++) {
        ulonglong2 c0 = A0, c1 = A1;
        if (k + 1 < K_) {
            const ulonglong2* r = (const ulonglong2*)(fb + (size_t)sidx[wid][k + 1] * C_);
            A0 = r[0]; A1 = r[1];
        }

        const float g = sgd[wid][k * H_ + cg];   // single head per lane (1 wf)
        unsigned long long gg;
        asm("mov.b64 %0, {%1, %1};" : "=l"(gg) : "f"(g));

        unsigned long long s0, s1, s2, s3;       // scaled channel-pairs
        asm("mul.rn.f32x2 %0, %1, %2;" : "=l"(s0) : "l"(c0.x), "l"(gg)); // ch {0,1}
        asm("mul.rn.f32x2 %0, %1, %2;" : "=l"(s1) : "l"(c0.y), "l"(gg)); // ch {2,3}
        asm("mul.rn.f32x2 %0, %1, %2;" : "=l"(s2) : "l"(c1.x), "l"(gg)); // ch {4,5}
        asm("mul.rn.f32x2 %0, %1, %2;" : "=l"(s3) : "l"(c1.y), "l"(gg)); // ch {6,7}

        // this lane's 4 W values: ONE LDS.128
        const float4 W = *(const float4*)(swn[wid] + k * CMID_ + 4 * jq);
        unsigned long long w0, w1, w2, w3;
        asm("mov.b64 %0, {%1, %1};" : "=l"(w0) : "f"(W.x));
        asm("mov.b64 %0, {%1, %1};" : "=l"(w1) : "f"(W.y));
        asm("mov.b64 %0, {%1, %1};" : "=l"(w2) : "f"(W.z));
        asm("mov.b64 %0, {%1, %1};" : "=l"(w3) : "f"(W.w));

        asm("fma.rn.f32x2 %0, %1, %2, %3;" : "=l"(acc[ 0]) : "l"(s0), "l"(w0), "l"(acc[ 0]));
        asm("fma.rn.f32x2 %0, %1, %2, %3;" : "=l"(acc[ 1]) : "l"(s0), "l"(w1), "l"(acc[ 1]));
        asm("fma.rn.f32x2 %0, %1, %2, %3;" : "=l"(acc[ 2]) : "l"(s0), "l"(w2), "l"(acc[ 2]));
        asm("fma.rn.f32x2 %0, %1, %2, %3;" : "=l"(acc[ 3]) : "l"(s0), "l"(w3), "l"(acc[ 3]));
        asm("fma.rn.f32x2 %0, %1, %2, %3;" : "=l"(acc[ 4]) : "l"(s1), "l"(w0), "l"(acc[ 4]));
        asm("fma.rn.f32x2 %0, %1, %2, %3;" : "=l"(acc[ 5]) : "l"(s1), "l"(w1), "l"(acc[ 5]));
        asm("fma.rn.f32x2 %0, %1, %2, %3;" : "=l"(acc[ 6]) : "l"(s1), "l"(w2), "l"(acc[ 6]));
        asm("fma.rn.f32x2 %0, %1, %2, %3;" : "=l"(acc[ 7]) : "l"(s1), "l"(w3), "l"(acc[ 7]));
        asm("fma.rn.f32x2 %0, %1, %2, %3;" : "=l"(acc[ 8]) : "l"(s2), "l"(w0), "l"(acc[ 8]));
        asm("fma.rn.f32x2 %0, %1, %2, %3;" : "=l"(acc[ 9]) : "l"(s2), "l"(w1), "l"(acc[ 9]));
        asm("fma.rn.f32x2 %0, %1, %2, %3;" : "=l"(acc[10]) : "l"(s2), "l"(w2), "l"(acc[10]));
        asm("fma.rn.f32x2 %0, %1, %2, %3;" : "=l"(acc[11]) : "l"(s2), "l"(w3), "l"(acc[11]));
        asm("fma.rn.f32x2 %0, %1, %2, %3;" : "=l"(acc[12]) : "l"(s3), "l"(w0), "l"(acc[12]));
        asm("fma.rn.f32x2 %0, %1, %2, %3;" : "=l"(acc[13]) : "l"(s3), "l"(w1), "l"(acc[13]));
        asm("fma.rn.f32x2 %0, %1, %2, %3;" : "=l"(acc[14]) : "l"(s3), "l"(w2), "l"(acc[14]));
        asm("fma.rn.f32x2 %0, %1, %2, %3;" : "=l"(acc[15]) : "l"(s3), "l"(w3), "l"(acc[15]));
    }

    // ---- epilogue: acc[i*4+j].lo -> row 8cg+2i, .hi -> row 8cg+2i+1, col 4jq+j
    float* o = out + (size_t)p * (C_ * CMID_) + (size_t)(8 * cg) * CMID_ + 4 * jq;
    #pragma unroll
    for (int i = 0; i < 4; i++) {
        float2 v0 = *(float2*)&acc[i * 4 + 0];
        float2 v1 = *(float2*)&acc[i * 4 + 1];
        float2 v2 = *(float2*)&acc[i * 4 + 2];
        float2 v3 = *(float2*)&acc[i * 4 + 3];
        *(float4*)(o + (2 * i) * CMID_)     = make_float4(v0.x, v1.x, v2.x, v3.x);
        *(float4*)(o + (2 * i + 1) * CMID_) = make_float4(v0.y, v1.y, v2.y, v3.y);
    }
}

extern "C" void kernel_launch(void* const* d_in, const int* in_sizes, int n_in,
                              void* d_out, int out_size) {
    const float* feat = (const float*)d_in[0];
    const void*  inds = d_in[1];
    const float* guid = (const float*)d_in[2];
    const float* wn   = (const float*)d_in[3];
    float* out = (float*)d_out;

    detect_idx_kernel<<<1, 32>>>((const unsigned int*)inds);
    pcf_kernel<<<(B_ * M_) / 4, 128>>>(feat, inds, guid, wn, out);
}